// round 15
// baseline (speedup 1.0000x reference)
#include <cuda_runtime.h>
#include <cuda_bf16.h>
#include <stdint.h>

// Problem constants
#define BB 2
#define HH 8
#define SS 2048
#define DD 16
#define BHN (BB*HH)

// Scratch (alloc-free rule: __device__ globals)
__device__ float g_M[BHN][DD][DD];   // M[bh][d1][d2] = sum_{k unmasked} K[k,d1]*V[k,d2]
__device__ float g_c[BHN][DD];       // c[bh][d]      = sum_{k masked}   V[k,d]
__device__ int   g_mask_u8;          // 1 if mask buffer is uint8-per-element, 0 if int32

// ---------- packed fp32x2 helpers (Blackwell FFMA2 via PTX) ----------
__device__ __forceinline__ unsigned long long pack2(float lo, float hi) {
    unsigned long long r;
    asm("mov.b64 %0, {%1, %2};" : "=l"(r) : "f"(lo), "f"(hi));
    return r;
}
__device__ __forceinline__ void fma2(unsigned long long& d, unsigned long long a,
                                     unsigned long long b) {
    asm("fma.rn.f32x2 %0, %1, %2, %0;" : "+l"(d) : "l"(a), "l"(b));
}
__device__ __forceinline__ float2 unpack2(unsigned long long v) {
    float lo, hi;
    asm("mov.b64 {%0, %1}, %2;" : "=f"(lo), "=f"(hi) : "l"(v));
    float2 f; f.x = lo; f.y = hi; return f;
}

// ============================================================================
// Kernel 0: detect mask storage layout.
// If bool uploaded as int32, every 32-bit word is 0 or 1. If uint8, words are
// 4 packed random 0/1 bytes -> w & ~1 is nonzero for ~7/8 of words; over 256
// sampled words misdetection probability is (1/8)^256 ~ 0.
// ============================================================================
__global__ void detect_mask_kernel(const int* __restrict__ mask) {
    int w = mask[threadIdx.x];                 // 256 threads, first 256 words
    int bad = (w & ~1) != 0;
    int any = __syncthreads_or(bad);
    if (threadIdx.x == 0) g_mask_u8 = any;
}

// mask row accessor: element k of the last-query mask row for batch-head bh
__device__ __forceinline__ int mask_at(const int* __restrict__ mask, int bh, int k) {
    const size_t rowoff = ((size_t)bh * SS + (SS - 1)) * (size_t)SS;
    if (g_mask_u8) {
        const unsigned char* m8 = (const unsigned char*)mask;
        return (int)m8[rowoff + (size_t)k];
    }
    return mask[rowoff + (size_t)k];
}

// ============================================================================
// Kernel 1: per (b,h) compute M (16x16) and c (16) from K, V, mask row.
// 16 blocks (one per bh), 256 threads = 16 (d1) x 16 (d2).
// ============================================================================
__global__ __launch_bounds__(256) void mc_kernel(const float* __restrict__ K,
                                                 const float* __restrict__ V,
                                                 const int* __restrict__ mask) {
    const int bh  = blockIdx.x;
    const int tid = threadIdx.x;
    const int d1  = tid >> 4;
    const int d2  = tid & 15;
    const float* Kb = K + (size_t)bh * SS * DD;
    const float* Vb = V + (size_t)bh * SS * DD;

    __shared__ float Ks[128 * DD];
    __shared__ float Vs[128 * DD];
    __shared__ float Ms[128];   // mask as float 0/1

    float accM = 0.f;
    float accC = 0.f;

    for (int k0 = 0; k0 < SS; k0 += 128) {
        for (int i = tid; i < 128 * DD; i += 256) {
            Ks[i] = Kb[(size_t)k0 * DD + i];
            Vs[i] = Vb[(size_t)k0 * DD + i];
        }
        if (tid < 128) Ms[tid] = mask_at(mask, bh, k0 + tid) ? 1.f : 0.f;
        __syncthreads();
#pragma unroll 8
        for (int kk = 0; kk < 128; ++kk) {
            float m  = Ms[kk];
            float kv = Ks[kk * DD + d1];
            float vv = Vs[kk * DD + d2];
            accM = fmaf((1.f - m) * kv, vv, accM);
            accC = fmaf(m, vv, accC);
        }
        __syncthreads();
    }
    g_M[bh][d1][d2] = accM;
    if (d1 == 0) g_c[bh][d2] = accC;
}

// ============================================================================
// Kernel 2: context[bh,q,d] = 0.25 * Q[bh,q,:] . M[bh,:,d]  - 1e9 * c[bh,d]
// grid (S/16, BH), 256 threads = 16 (q) x 16 (d).
// ============================================================================
__global__ __launch_bounds__(256) void ctx_kernel(const float* __restrict__ Q,
                                                  float* __restrict__ out_ctx) {
    const int bh = blockIdx.y;
    const int q0 = blockIdx.x * 16;
    const int tid = threadIdx.x;
    const int tq = tid >> 4;
    const int d  = tid & 15;

    __shared__ float Ms[DD][DD];
    __shared__ float cs[DD];
    __shared__ float Qs[16][DD];

    Ms[tq][d] = g_M[bh][tq][d];
    if (tid < DD) cs[tid] = g_c[bh][tid];
    Qs[tq][d] = Q[((size_t)bh * SS + q0 + tq) * DD + d];
    __syncthreads();

    float s = 0.f;
#pragma unroll
    for (int d1 = 0; d1 < DD; ++d1) s = fmaf(Qs[tq][d1], Ms[d1][d], s);

    out_ctx[((size_t)bh * SS + q0 + tq) * DD + d] = 0.25f * s - 1e9f * cs[d];
}

// ============================================================================
// Kernel 3: scores[bh,q,k] = mask[bh,k] ? -1e9 : 0.25 * Q[bh,q,:].K[bh,k,:]
// Tile: block = 256 threads handles 64 q rows; loop over k in 64-wide tiles.
// Thread (tq = tid>>4, tk = tid&15): 4 q rows (as 2 packed pairs) x 4 k cols
// (strided k = tk + 16*j for conflict-free LDS.64).
// K values are stored in SMEM pre-duplicated as (v,v) fp32x2 packs so the
// inner loop is pure LDS.64 + FFMA2. Q is pre-scaled by 0.25 and kept packed
// in registers for the whole block. Score stores use st.global.cs (streaming,
// evict-first) -- 268 MB write-once output must not thrash L2 for K re-reads.
// ============================================================================
#define TQ 64
#define TK 64

__global__ __launch_bounds__(256, 2) void scores_kernel(const float* __restrict__ Q,
                                                        const float* __restrict__ K,
                                                        const int* __restrict__ mask,
                                                        float* __restrict__ out_scores) {
    const int bh  = blockIdx.y;
    const int q0  = blockIdx.x * TQ;
    const int tid = threadIdx.x;
    const int tk  = tid & 15;
    const int tq  = tid >> 4;

    const float* Qb = Q + (size_t)bh * SS * DD;
    const float* Kb = K + (size_t)bh * SS * DD;
    float* outb = out_scores + (size_t)bh * SS * SS;

    __shared__ unsigned long long Kdup[DD][TK];   // [d][k] : (K[k,d], K[k,d])
    __shared__ int mk[TK];

    // ---- load this block's 4 Q rows (per thread) into packed, pre-scaled regs
    unsigned long long q2[2][DD];
    {
        float qrow[4][DD];
#pragma unroll
        for (int r = 0; r < 4; ++r) {
            const float4* p = (const float4*)(Qb + (size_t)(q0 + tq * 4 + r) * DD);
#pragma unroll
            for (int g = 0; g < 4; ++g) {
                float4 v = p[g];
                qrow[r][g * 4 + 0] = v.x; qrow[r][g * 4 + 1] = v.y;
                qrow[r][g * 4 + 2] = v.z; qrow[r][g * 4 + 3] = v.w;
            }
        }
#pragma unroll
        for (int p2 = 0; p2 < 2; ++p2)
#pragma unroll
            for (int d = 0; d < DD; ++d)
                q2[p2][d] = pack2(qrow[2 * p2][d] * 0.25f, qrow[2 * p2 + 1][d] * 0.25f);
    }

    for (int k0 = 0; k0 < SS; k0 += TK) {
        // ---- fill Kdup (transposed + duplicated) : thread loads one float4 of a K row
        {
            const int r  = tid >> 2;            // k row within tile, 0..63
            const int dg = (tid & 3) * 4;       // d group
            float4 v = *(const float4*)(Kb + (size_t)(k0 + r) * DD + dg);
            Kdup[dg + 0][r] = pack2(v.x, v.x);
            Kdup[dg + 1][r] = pack2(v.y, v.y);
            Kdup[dg + 2][r] = pack2(v.z, v.z);
            Kdup[dg + 3][r] = pack2(v.w, v.w);
            if (tid < TK) mk[tid] = mask_at(mask, bh, k0 + tid);
        }
        __syncthreads();

        unsigned long long acc[2][4];
#pragma unroll
        for (int p = 0; p < 2; ++p)
#pragma unroll
            for (int j = 0; j < 4; ++j) acc[p][j] = 0ull;

#pragma unroll
        for (int d = 0; d < DD; ++d) {
            unsigned long long kv0 = Kdup[d][tk +  0];
            unsigned long long kv1 = Kdup[d][tk + 16];
            unsigned long long kv2 = Kdup[d][tk + 32];
            unsigned long long kv3 = Kdup[d][tk + 48];
            fma2(acc[0][0], kv0, q2[0][d]);
            fma2(acc[0][1], kv1, q2[0][d]);
            fma2(acc[0][2], kv2, q2[0][d]);
            fma2(acc[0][3], kv3, q2[0][d]);
            fma2(acc[1][0], kv0, q2[1][d]);
            fma2(acc[1][1], kv1, q2[1][d]);
            fma2(acc[1][2], kv2, q2[1][d]);
            fma2(acc[1][3], kv3, q2[1][d]);
        }

        bool m0 = mk[tk +  0] != 0;
        bool m1 = mk[tk + 16] != 0;
        bool m2 = mk[tk + 32] != 0;
        bool m3 = mk[tk + 48] != 0;

#pragma unroll
        for (int p = 0; p < 2; ++p) {
            float2 s0 = unpack2(acc[p][0]);
            float2 s1 = unpack2(acc[p][1]);
            float2 s2 = unpack2(acc[p][2]);
            float2 s3 = unpack2(acc[p][3]);
            float* rowA = outb + (size_t)(q0 + tq * 4 + 2 * p) * SS + k0 + tk;
            float* rowB = rowA + SS;
            __stcs(rowA +  0, m0 ? -1e9f : s0.x);  __stcs(rowB +  0, m0 ? -1e9f : s0.y);
            __stcs(rowA + 16, m1 ? -1e9f : s1.x);  __stcs(rowB + 16, m1 ? -1e9f : s1.y);
            __stcs(rowA + 32, m2 ? -1e9f : s2.x);  __stcs(rowB + 32, m2 ? -1e9f : s2.y);
            __stcs(rowA + 48, m3 ? -1e9f : s3.x);  __stcs(rowB + 48, m3 ? -1e9f : s3.y);
        }
        __syncthreads();
    }
}

// ============================================================================
// kernel_launch
// inputs (metadata order): Q [B,H,S,D] f32, K [B,H,S,D] f32, V [B,H,S,D] f32,
//                          attn_mask [B,H,S,S] bool (layout auto-detected:
//                          int32-per-element or uint8-per-element)
// output: context [B,H,S,D] f32 then scores [B,H,S,S] f32, concatenated.
// ============================================================================
extern "C" void kernel_launch(void* const* d_in, const int* in_sizes, int n_in,
                              void* d_out, int out_size) {
    const float* Q = (const float*)d_in[0];
    const float* K = (const float*)d_in[1];
    const float* V = (const float*)d_in[2];
    const int* mask = (const int*)d_in[3];

    float* out_ctx    = (float*)d_out;
    float* out_scores = out_ctx + (size_t)BHN * SS * DD;

    // mask layout detection (writes g_mask_u8; ordered before consumers in-stream)
    detect_mask_kernel<<<1, 256>>>(mask);

    // M/c reduction, then context (depends on M/c)
    mc_kernel<<<BHN, 256>>>(K, V, mask);
    {
        dim3 grid(SS / 16, BHN);
        ctx_kernel<<<grid, 256>>>(Q, out_ctx);
    }
    // scores (independent, dominant cost)
    {
        dim3 grid(SS / TQ, BHN);
        scores_kernel<<<grid, 256>>>(Q, K, mask, out_scores);
    }
}

// round 17
// speedup vs baseline: 1.0412x; 1.0412x over previous
#include <cuda_runtime.h>
#include <cuda_bf16.h>
#include <stdint.h>

// Problem constants
#define BB 2
#define HH 8
#define SS 2048
#define DD 16
#define BHN (BB*HH)
#define MCCH 8            // mc_kernel k-chunks

// Scratch (alloc-free rule: __device__ globals)
__device__ float g_Mp[MCCH][BHN][DD][DD]; // partial M per k-chunk
__device__ float g_cp[MCCH][BHN][DD];     // partial c per k-chunk
__device__ int   g_mask_u8;               // 1 if mask is uint8-per-element, 0 if int32

typedef unsigned long long ull;

// ---------- packed fp32x2 helpers (Blackwell FFMA2 via PTX) ----------
__device__ __forceinline__ ull pack2(float lo, float hi) {
    ull r;
    asm("mov.b64 %0, {%1, %2};" : "=l"(r) : "f"(lo), "f"(hi));
    return r;
}
__device__ __forceinline__ void fma2(ull& d, ull a, ull b) {
    asm("fma.rn.f32x2 %0, %1, %2, %0;" : "+l"(d) : "l"(a), "l"(b));
}
__device__ __forceinline__ ull fma2full(ull a, ull b, ull c) {   // a*b + c
    ull d;
    asm("fma.rn.f32x2 %0, %1, %2, %3;" : "=l"(d) : "l"(a), "l"(b), "l"(c));
    return d;
}

// ============================================================================
// Kernel 0: detect mask storage layout (int32 words all 0/1 vs packed bytes).
// ============================================================================
__global__ void detect_mask_kernel(const int* __restrict__ mask) {
    int w = mask[threadIdx.x];
    int bad = (w & ~1) != 0;
    int any = __syncthreads_or(bad);
    if (threadIdx.x == 0) g_mask_u8 = any;
}

__device__ __forceinline__ int mask_at(const int* __restrict__ mask, int bh, int k) {
    const size_t rowoff = ((size_t)bh * SS + (SS - 1)) * (size_t)SS;
    if (g_mask_u8) {
        const unsigned char* m8 = (const unsigned char*)mask;
        return (int)m8[rowoff + (size_t)k];
    }
    return mask[rowoff + (size_t)k];
}

// ============================================================================
// Kernel 1: partial M (16x16) and c (16) per (bh, k-chunk of 256).
// grid (BHN, MCCH), 256 threads = 16 (d1) x 16 (d2).
// ============================================================================
__global__ __launch_bounds__(256) void mc_kernel(const float* __restrict__ K,
                                                 const float* __restrict__ V,
                                                 const int* __restrict__ mask) {
    const int bh  = blockIdx.x;
    const int ch  = blockIdx.y;
    const int tid = threadIdx.x;
    const int d1  = tid >> 4;
    const int d2  = tid & 15;
    const float* Kb = K + (size_t)bh * SS * DD;
    const float* Vb = V + (size_t)bh * SS * DD;

    __shared__ float Ks[128 * DD];
    __shared__ float Vs[128 * DD];
    __shared__ float Ms[128];

    float accM = 0.f;
    float accC = 0.f;

    const int kbeg = ch * (SS / MCCH);            // 256-wide chunk
    for (int k0 = kbeg; k0 < kbeg + SS / MCCH; k0 += 128) {
        for (int i = tid; i < 128 * DD; i += 256) {
            Ks[i] = Kb[(size_t)k0 * DD + i];
            Vs[i] = Vb[(size_t)k0 * DD + i];
        }
        if (tid < 128) Ms[tid] = mask_at(mask, bh, k0 + tid) ? 1.f : 0.f;
        __syncthreads();
#pragma unroll 8
        for (int kk = 0; kk < 128; ++kk) {
            float m  = Ms[kk];
            float kv = Ks[kk * DD + d1];
            float vv = Vs[kk * DD + d2];
            accM = fmaf((1.f - m) * kv, vv, accM);
            accC = fmaf(m, vv, accC);
        }
        __syncthreads();
    }
    g_Mp[ch][bh][d1][d2] = accM;
    if (d1 == 0) g_cp[ch][bh][d2] = accC;
}

// ============================================================================
// Kernel 2: context[bh,q,d] = 0.25 * Q[bh,q,:] . M[bh,:,d] - 1e9 * c[bh,d]
// grid (S/16, BH), 256 threads = 16 (q) x 16 (d). Sums MCCH partials.
// ============================================================================
__global__ __launch_bounds__(256) void ctx_kernel(const float* __restrict__ Q,
                                                  float* __restrict__ out_ctx) {
    const int bh = blockIdx.y;
    const int q0 = blockIdx.x * 16;
    const int tid = threadIdx.x;
    const int tq = tid >> 4;
    const int d  = tid & 15;

    __shared__ float Ms[DD][DD];
    __shared__ float cs[DD];
    __shared__ float Qs[16][DD];

    {
        float m = 0.f;
#pragma unroll
        for (int ch = 0; ch < MCCH; ++ch) m += g_Mp[ch][bh][tq][d];
        Ms[tq][d] = m;
    }
    if (tid < DD) {
        float c = 0.f;
#pragma unroll
        for (int ch = 0; ch < MCCH; ++ch) c += g_cp[ch][bh][tid];
        cs[tid] = c;
    }
    Qs[tq][d] = Q[((size_t)bh * SS + q0 + tq) * DD + d];
    __syncthreads();

    float s = 0.f;
#pragma unroll
    for (int d1 = 0; d1 < DD; ++d1) s = fmaf(Qs[tq][d1], Ms[d1][d], s);

    out_ctx[((size_t)bh * SS + q0 + tq) * DD + d] = 0.25f * s - 1e9f * cs[d];
}

// ============================================================================
// Kernel 3 (v2): scores[bh,q,k] = mask[k] ? -1e9 : 0.25 * Q[q,:].K[k,:]
//
// k-packed: accumulator pair = (s[q][2p], s[q][2p+1]) for k-pair p.
// Kp[d][p]   = (K[2p,d],   K[2p+1,d])   (fp32x2, built per k-tile)
// Qd[d][q]   = (0.25Q[q,d], 0.25Q[q,d]) (fp32x2 dup, built once per block,
//                                        read broadcast: lanes share tq)
// Thread (tk=tid&15, tq=tid>>4): 4 q-rows (4tq..4tq+3) x 4 strided k-pairs
// (p = tk+16j). Per d: 4 LDS.64 (K, broadcast x2) + 2 LDS.128 (Q, broadcast
// x16) + 16 FFMA2 -> fma-dominant instruction mix.
// Mask applied branchlessly: s_final = s*(1-m) + (-1e9)*m  (exact both ways).
// Stores: pair == 2 consecutive output floats -> 8 coalesced STG.64 (evict-
// first streaming) per thread per tile.
// ============================================================================
#define TQ 64
#define TK 128
#define KP 64            // k-pairs per tile
#define KPP 66           // padded row (bank-conflict-free STS, 16B-aligned)

__global__ __launch_bounds__(256, 3) void scores_kernel(const float* __restrict__ Q,
                                                        const float* __restrict__ K,
                                                        const int* __restrict__ mask,
                                                        float* __restrict__ out_scores) {
    const int bh  = blockIdx.y;
    const int q0  = blockIdx.x * TQ;
    const int tid = threadIdx.x;
    const int tk  = tid & 15;
    const int tq  = tid >> 4;

    const float* Qb = Q + (size_t)bh * SS * DD;
    const float* Kb = K + (size_t)bh * SS * DD;
    float* outb = out_scores + (size_t)bh * SS * SS;

    __shared__ ull Kp[DD][KPP];     // [d][pair]
    __shared__ ull Qd[DD][TQ];      // [d][q] duplicated, pre-scaled
    __shared__ ull mulp[KP];        // (1-m, 1-m') per pair
    __shared__ ull addp[KP];        // (-1e9*m, -1e9*m') per pair

    // ---- build Qd once per block (read inside the tile loop only)
    for (int i = tid; i < DD * TQ; i += 256) {
        int d = i >> 6;             // i / TQ
        int q = i & (TQ - 1);
        float v = Qb[(size_t)(q0 + q) * DD + d] * 0.25f;
        Qd[d][q] = pack2(v, v);
    }

    for (int k0 = 0; k0 < SS; k0 += TK) {
        // ---- build Kp (transpose 2 k-rows into fp32x2 pairs) + mask pairs
        {
            const int p  = tid >> 2;            // pair 0..63
            const int dg = (tid & 3) * 4;       // d group {0,4,8,12}
            float4 a = *(const float4*)(Kb + (size_t)(k0 + 2 * p) * DD + dg);
            float4 b = *(const float4*)(Kb + (size_t)(k0 + 2 * p + 1) * DD + dg);
            Kp[dg + 0][p] = pack2(a.x, b.x);
            Kp[dg + 1][p] = pack2(a.y, b.y);
            Kp[dg + 2][p] = pack2(a.z, b.z);
            Kp[dg + 3][p] = pack2(a.w, b.w);
            if (tid < KP) {
                int kk = k0 + 2 * tid;
                int m0 = mask_at(mask, bh, kk)     != 0;
                int m1 = mask_at(mask, bh, kk + 1) != 0;
                mulp[tid] = pack2(m0 ? 0.f : 1.f,  m1 ? 0.f : 1.f);
                addp[tid] = pack2(m0 ? -1e9f : 0.f, m1 ? -1e9f : 0.f);
            }
        }
        __syncthreads();

        ull acc[4][4];
#pragma unroll
        for (int r = 0; r < 4; ++r)
#pragma unroll
            for (int j = 0; j < 4; ++j) acc[r][j] = 0ull;

#pragma unroll
        for (int d = 0; d < DD; ++d) {
            ulonglong2 qa = *(const ulonglong2*)&Qd[d][4 * tq];      // rows 0,1
            ulonglong2 qb = *(const ulonglong2*)&Qd[d][4 * tq + 2];  // rows 2,3
            ull k0v = Kp[d][tk];
            ull k1v = Kp[d][tk + 16];
            ull k2v = Kp[d][tk + 32];
            ull k3v = Kp[d][tk + 48];
            fma2(acc[0][0], k0v, qa.x); fma2(acc[0][1], k1v, qa.x);
            fma2(acc[0][2], k2v, qa.x); fma2(acc[0][3], k3v, qa.x);
            fma2(acc[1][0], k0v, qa.y); fma2(acc[1][1], k1v, qa.y);
            fma2(acc[1][2], k2v, qa.y); fma2(acc[1][3], k3v, qa.y);
            fma2(acc[2][0], k0v, qb.x); fma2(acc[2][1], k1v, qb.x);
            fma2(acc[2][2], k2v, qb.x); fma2(acc[2][3], k3v, qb.x);
            fma2(acc[3][0], k0v, qb.y); fma2(acc[3][1], k1v, qb.y);
            fma2(acc[3][2], k2v, qb.y); fma2(acc[3][3], k3v, qb.y);
        }

        // ---- masked epilogue + 64-bit streaming stores
        ull mu0 = mulp[tk],      mu1 = mulp[tk + 16];
        ull mu2 = mulp[tk + 32], mu3 = mulp[tk + 48];
        ull ad0 = addp[tk],      ad1 = addp[tk + 16];
        ull ad2 = addp[tk + 32], ad3 = addp[tk + 48];

#pragma unroll
        for (int r = 0; r < 4; ++r) {
            float* row = outb + (size_t)(q0 + 4 * tq + r) * SS + k0;
            __stcs((ull*)(row + 2 * tk),        fma2full(acc[r][0], mu0, ad0));
            __stcs((ull*)(row + 2 * (tk + 16)), fma2full(acc[r][1], mu1, ad1));
            __stcs((ull*)(row + 2 * (tk + 32)), fma2full(acc[r][2], mu2, ad2));
            __stcs((ull*)(row + 2 * (tk + 48)), fma2full(acc[r][3], mu3, ad3));
        }
        __syncthreads();
    }
}

// ============================================================================
// kernel_launch
// inputs: Q [B,H,S,D] f32, K f32, V f32, attn_mask bool (layout auto-detected)
// output: context [B,H,S,D] f32 then scores [B,H,S,S] f32, concatenated.
// ============================================================================
extern "C" void kernel_launch(void* const* d_in, const int* in_sizes, int n_in,
                              void* d_out, int out_size) {
    const float* Q = (const float*)d_in[0];
    const float* K = (const float*)d_in[1];
    const float* V = (const float*)d_in[2];
    const int* mask = (const int*)d_in[3];

    float* out_ctx    = (float*)d_out;
    float* out_scores = out_ctx + (size_t)BHN * SS * DD;

    // mask layout detection (ordered before consumers in-stream)
    detect_mask_kernel<<<1, 256>>>(mask);

    // M/c partial reduction (parallel over k-chunks), then context
    {
        dim3 grid(BHN, MCCH);
        mc_kernel<<<grid, 256>>>(K, V, mask);
    }
    {
        dim3 grid(SS / 16, BHN);
        ctx_kernel<<<grid, 256>>>(Q, out_ctx);
    }
    // scores (dominant cost)
    {
        dim3 grid(SS / TQ, BHN);
        scores_kernel<<<grid, 256>>>(Q, K, mask, out_scores);
    }
}